// round 7
// baseline (speedup 1.0000x reference)
#include <cuda_runtime.h>
#include <float.h>
#include <math.h>

// Problem constants
#define BATCH 2
#define NPT   64      // user inputs per batch
#define CCH   256     // feature channels
#define KCLS  10      // classes
#define KT    32      // K-tile per pipeline stage
#define NSPL  8       // class-max partitions in k_cor (2 halves x 4 warps)

// Separable Gaussian tables: g_ex[lvl][b][px][64n] (inv folded), g_ey[lvl][b][py][64n]
__device__ __forceinline__ int etab_off(int level, int b) {
    return level == 0 ? b * 4096 : (level == 1 ? 8192 + b * 2048 : 12288 + b * 1024);
}
__device__ __forceinline__ int part_off(int level) {
    return level == 0 ? 0 : (level == 1 ? 1048576 : 1572864);
}

// Scratch (device globals; no allocation allowed)
__device__ float g_ex[14336];
__device__ float g_ey[14336];
__device__ float g_part[1835008];                     // K-split partial templates
__device__ float g_tmplD[3 * BATCH * CCH * 2 * NPT];  // template DUPLICATED [lvl][b][c][2n]
__device__ float g_cmax[NSPL * BATCH * KCLS * 5376];  // per-partition class max

// int64-vs-int32 detection: labels in [1,10]; if int64 LE, word 1 == high(label0) == 0.
__device__ __forceinline__ bool detect64(const int* labels_i32) {
    return labels_i32[1] == 0;
}
__device__ __forceinline__ int geti(const int* p, int i, bool is64) {
    return p[is64 ? 2 * i : i];
}

// cp.async helpers
__device__ __forceinline__ void cp_async16(void* smem_dst, const void* gsrc) {
    unsigned s = (unsigned)__cvta_generic_to_shared(smem_dst);
    asm volatile("cp.async.cg.shared.global [%0], [%1], 16;\n" :: "r"(s), "l"(gsrc));
}
__device__ __forceinline__ void cp_commit() {
    asm volatile("cp.async.commit_group;\n" ::: "memory");
}
__device__ __forceinline__ void cp_wait1() {
    asm volatile("cp.async.wait_group 1;\n" ::: "memory");
}
__device__ __forceinline__ void cp_wait0() {
    asm volatile("cp.async.wait_group 0;\n" ::: "memory");
}

// packed f32x2 fma: d = a * b + d  (componentwise, round-to-nearest)
__device__ __forceinline__ void ffma2(unsigned long long& d,
                                      unsigned long long a,
                                      unsigned long long b) {
    asm("fma.rn.f32x2 %0, %1, %2, %0;" : "+l"(d) : "l"(a), "l"(b));
}
__device__ __forceinline__ float2 unpack2(unsigned long long v) {
    float2 r;
    asm("mov.b64 {%0, %1}, %2;" : "=f"(r.x), "=f"(r.y) : "l"(v));
    return r;
}

// ---------------------------------------------------------------------------
// K0: separable Gaussian tables. grid 384 = 3 lvl x 2 b x 64 n, 64 thr.
// ex[px][n] = exp(ax dx^2) / (Sx*Sy + 1e-8)  (0 if invalid); ey[py][n] = exp.
// ---------------------------------------------------------------------------
__global__ void k_heat(const float* __restrict__ centers,
                       const int* __restrict__ idx_i32,
                       const int* __restrict__ labels_i32) {
    __shared__ float redx[64], redy[64];

    int blk = blockIdx.x;
    int level = blk >> 7;
    int rem = blk & 127;
    int b = rem >> 6, n = rem & 63;

    int hd = 64 >> level;
    int scale = 8 << level;

    bool is64 = detect64(labels_i32);
    bool valid = geti(idx_i32, b * NPT + n, is64) != -1;
    float cx = centers[(b * NPT + n) * 2 + 0];
    float cy = centers[(b * NPT + n) * 2 + 1];
    const float alpha = -0.5f / 9.0f;  // sigma = 3

    int t = threadIdx.x;
    float exv = 0.f, eyv = 0.f;
    if (t < hd) {
        float coord = t * (float)scale + 0.5f;
        float dx = coord - cx, dy = coord - cy;
        exv = __expf(alpha * dx * dx);
        eyv = __expf(alpha * dy * dy);
    }
    redx[t] = exv; redy[t] = eyv;
    __syncthreads();
    for (int s = 32; s > 0; s >>= 1) {
        if (t < s) { redx[t] += redx[t + s]; redy[t] += redy[t + s]; }
        __syncthreads();
    }
    float inv = 1.0f / (redx[0] * redy[0] + 1e-8f);

    int off = etab_off(level, b);
    if (t < hd) {
        g_ex[off + t * 64 + n] = valid ? exv * inv : 0.f;
        g_ey[off + t * 64 + n] = eyv;
    }
}

// ---------------------------------------------------------------------------
// K1a: template GEMM partials, pipelined, f32x2 inner loop.
// T[n][c] = sum_p heat[n][p]*feat[c][p]. sA computed on the fly (DUPLICATED
// n-pairs); sB (feat) transpose-staged (c contiguous -> natural c-pairs).
// grid 448: lvl0 256 (4ct x 32ks x 2b, kchunk=128), lvl1 128, lvl2 64. 256 thr.
// Thread: 4n x 4c = 4n x 2 c-pairs -> 8 ull accumulators.
// ---------------------------------------------------------------------------
__global__ void __launch_bounds__(256) k_tmpl_part(
                            const float* __restrict__ x0,
                            const float* __restrict__ x1,
                            const float* __restrict__ x2) {
    __shared__ float sA[2][KT][136];  // [buf][k][2n dup] (+pad)
    __shared__ float sB[2][KT][68];   // [buf][k][c_local]

    int blk = blockIdx.x;
    int level, lb;
    if (blk < 256)      { level = 0; lb = blk; }
    else if (blk < 384) { level = 1; lb = blk - 256; }
    else                { level = 2; lb = blk - 384; }

    int ct, ks, b, kchunk, HW;
    if (level == 0)      { ct = lb & 3; ks = (lb >> 2) & 31; b = lb >> 7; kchunk = 128; HW = 4096; }
    else if (level == 1) { ct = lb & 3; ks = (lb >> 2) & 15; b = lb >> 6; kchunk = 64;  HW = 1024; }
    else                 { ct = lb & 3; ks = (lb >> 2) & 7;  b = lb >> 5; kchunk = 32;  HW = 256;  }
    int S = kchunk / KT;              // stages: 4 / 2 / 1
    int p0 = ks * kchunk;
    int hdm = (64 >> level) - 1;      // px mask
    int hdsh = 6 - level;             // py shift

    const float* feat = (level == 0) ? x0 : (level == 1) ? x1 : x2;
    const float* exb = g_ex + etab_off(level, b);
    const float* eyb = g_ey + etab_off(level, b);

    int tid = threadIdx.x;
    int ty = tid >> 4, tx = tid & 15;

    // sA compute-staging: 2 rows x 4 n per thread
    int ar0 = tid >> 4, anq = (tid & 15) * 4;
    int ar1 = ar0 + 16;

    // sB transpose staging: thread -> (c_row, kseg)
    int crow = tid >> 2;              // 0..63
    int kseg = (tid & 3) * 8;
    const float* fb = feat + (size_t)(b * CCH + ct * 64 + crow) * HW + p0 + kseg;

    float4 rb0, rb1, rex0, rey0, rex1, rey1;

#define LOAD_STAGE_REGS(pbase)                                            \
    {                                                                     \
        int pA0 = (pbase) + ar0, pA1 = (pbase) + ar1;                     \
        rex0 = *(const float4*)&exb[(pA0 & hdm) * 64 + anq];              \
        rey0 = *(const float4*)&eyb[(pA0 >> hdsh) * 64 + anq];            \
        rex1 = *(const float4*)&exb[(pA1 & hdm) * 64 + anq];              \
        rey1 = *(const float4*)&eyb[(pA1 >> hdsh) * 64 + anq];            \
    }
#define STORE_STAGE(bufi)                                                 \
    {                                                                     \
        float v0 = rex0.x * rey0.x, v1 = rex0.y * rey0.y;                 \
        float v2 = rex0.z * rey0.z, v3 = rex0.w * rey0.w;                 \
        *(float4*)&sA[bufi][ar0][anq * 2]     = make_float4(v0, v0, v1, v1); \
        *(float4*)&sA[bufi][ar0][anq * 2 + 4] = make_float4(v2, v2, v3, v3); \
        v0 = rex1.x * rey1.x; v1 = rex1.y * rey1.y;                       \
        v2 = rex1.z * rey1.z; v3 = rex1.w * rey1.w;                       \
        *(float4*)&sA[bufi][ar1][anq * 2]     = make_float4(v0, v0, v1, v1); \
        *(float4*)&sA[bufi][ar1][anq * 2 + 4] = make_float4(v2, v2, v3, v3); \
        _Pragma("unroll")                                                 \
        for (int i = 0; i < 4; i++) {                                     \
            sB[bufi][kseg + i][crow] = ((const float*)&rb0)[i];           \
            sB[bufi][kseg + 4 + i][crow] = ((const float*)&rb1)[i];       \
        }                                                                 \
    }

    // prologue: stage 0
    LOAD_STAGE_REGS(p0);
    rb0 = *(const float4*)(fb + 0);
    rb1 = *(const float4*)(fb + 4);
    STORE_STAGE(0);
    __syncthreads();

    unsigned long long acc2[4][2];
#pragma unroll
    for (int i = 0; i < 4; i++) { acc2[i][0] = 0ULL; acc2[i][1] = 0ULL; }

    int n0 = ty * 4, c0 = tx * 4;

    for (int kt = 0; kt < S; kt++) {
        int buf = kt & 1, nb = buf ^ 1;
        if (kt < S - 1) {
            LOAD_STAGE_REGS(p0 + (kt + 1) * KT);
            rb0 = *(const float4*)(fb + (kt + 1) * KT + 0);
            rb1 = *(const float4*)(fb + (kt + 1) * KT + 4);
        }

#pragma unroll
        for (int k = 0; k < KT; k++) {
            ulonglong2 A01 = *(const ulonglong2*)&sA[buf][k][n0 * 2];      // (a0a0,a1a1)
            ulonglong2 A23 = *(const ulonglong2*)&sA[buf][k][n0 * 2 + 4];  // (a2a2,a3a3)
            ulonglong2 Bp  = *(const ulonglong2*)&sB[buf][k][c0];          // (b0b1,b2b3)
            ffma2(acc2[0][0], A01.x, Bp.x); ffma2(acc2[0][1], A01.x, Bp.y);
            ffma2(acc2[1][0], A01.y, Bp.x); ffma2(acc2[1][1], A01.y, Bp.y);
            ffma2(acc2[2][0], A23.x, Bp.x); ffma2(acc2[2][1], A23.x, Bp.y);
            ffma2(acc2[3][0], A23.y, Bp.x); ffma2(acc2[3][1], A23.y, Bp.y);
        }

        if (kt < S - 1) {
            STORE_STAGE(nb);
            __syncthreads();
        }
    }
#undef LOAD_STAGE_REGS
#undef STORE_STAGE

    // write 4x4 partial
    float* pp = g_part + part_off(level) + (size_t)((ks * BATCH + b) * NPT) * CCH + ct * 64;
#pragma unroll
    for (int i = 0; i < 4; i++) {
        float2 lo = unpack2(acc2[i][0]);
        float2 hi = unpack2(acc2[i][1]);
        *(float4*)&pp[(size_t)(n0 + i) * CCH + c0] = make_float4(lo.x, lo.y, hi.x, hi.y);
    }
}

// ---------------------------------------------------------------------------
// K1b: reduce partials over ks, write DUPLICATED template [lvl][b][c][2n]
// grid 384 = 3 x 2 x 64 (n), 256 thr (c)
// ---------------------------------------------------------------------------
__global__ void k_tmpl_reduce() {
    int blk = blockIdx.x;
    int level = blk / 128;
    int rem = blk - level * 128;
    int b = rem >> 6, n = rem & 63;
    int KS = (level == 0) ? 32 : (level == 1) ? 16 : 8;
    int c = threadIdx.x;

    const float* pbase = g_part + part_off(level);
    float s = 0.f;
    for (int ks = 0; ks < KS; ks++)
        s += pbase[(size_t)((ks * BATCH + b) * NPT + n) * CCH + c];

    float* td = g_tmplD + (size_t)((level * BATCH + b) * CCH + c) * (2 * NPT);
    *(float2*)&td[2 * n] = make_float2(s, s);
}

// ---------------------------------------------------------------------------
// K2: correlation as cp.async GEMM with f32x2 inner loop.
// Block 128 thr (4 warps), tile 32n(half) x 64px, 2 px/thread packed in ull.
// sA staged DUPLICATED from g_tmplD. Per k: 4 bcast LDS.128 + 1 LDS.64 + 8 FFMA2.
// half==0 blocks copy feat -> out from staged sB. Partition = half*4 + w.
// grid 336: lvl0 256 (64 px-tiles x 2 b x 2 half), lvl1 64, lvl2 16.
// ---------------------------------------------------------------------------
__global__ void __launch_bounds__(128) k_cor(
                      const float* __restrict__ x0,
                      const float* __restrict__ x1,
                      const float* __restrict__ x2,
                      const int* __restrict__ labels_i32,
                      float* __restrict__ out) {
    __shared__ float sA[2][KT][64];   // [buf][k=c][2n dup, 32 n]
    __shared__ float sB[2][KT][64];   // [buf][k=c][px]
    __shared__ int lab[32];

    int blk = blockIdx.x;
    int level, lb;
    if (blk < 256)      { level = 0; lb = blk; }
    else if (blk < 320) { level = 1; lb = blk - 256; }
    else                { level = 2; lb = blk - 320; }

    int half = lb & 1;
    int b = (lb >> 1) & 1;
    int tile = lb >> 2;
    int HW = 4096 >> (2 * level);
    int px0 = tile * 64;
    int oOff = (level == 0) ? 0 : (level == 1) ? 2179072 : 2723840;
    int q5376 = (level == 0) ? 0 : (level == 1) ? 4096 : 5120;
    const float* feat = (level == 0) ? x0 : (level == 1) ? x1 : x2;

    int tid = threadIdx.x;
    int lane = tid & 31;
    int w = tid >> 5;

    const float* tsrc = g_tmplD + (size_t)(level * BATCH + b) * CCH * (2 * NPT)
                        + half * 64;                 // duplicated slice [c][64]
    const float* fbase = feat + (size_t)b * CCH * HW + px0;
    float* obase = out + oOff + (size_t)b * (CCH + KCLS) * HW + px0;

    if (tid < 32) {
        bool is64 = detect64(labels_i32);
        lab[tid] = geti(labels_i32, b * NPT + half * 32 + tid, is64);
    }

    // sA: 512 f4/stage (4/thread); sB: 512 f4/stage (4/thread)
#define STAGE_CP(bufi, c0base)                                                      \
    {                                                                               \
        _Pragma("unroll")                                                           \
        for (int j = 0; j < 4; j++) {                                               \
            int idx = tid + j * 128;                                                \
            int r = idx >> 4, cq = (idx & 15) * 4;                                  \
            cp_async16(&sA[bufi][r][cq],                                            \
                       tsrc + (size_t)((c0base) + r) * (2 * NPT) + cq);             \
        }                                                                           \
        _Pragma("unroll")                                                           \
        for (int j = 0; j < 4; j++) {                                               \
            int idx = tid + j * 128;                                                \
            int r = idx >> 4, cc = (idx & 15) * 4;                                  \
            cp_async16(&sB[bufi][r][cc], fbase + (size_t)((c0base) + r) * HW + cc); \
        }                                                                           \
        cp_commit();                                                                \
    }

    STAGE_CP(0, 0);

    unsigned long long acc2[8];
#pragma unroll
    for (int i = 0; i < 8; i++) acc2[i] = 0ULL;

    int nw0 = w * 8;   // this warp's first n (of 32 in the half)

    for (int kt = 0; kt < CCH / KT; kt++) {
        int buf = kt & 1;
        if (kt < CCH / KT - 1) {
            STAGE_CP(buf ^ 1, (kt + 1) * KT);
            cp_wait1();
        } else {
            cp_wait0();
        }
        __syncthreads();

#pragma unroll
        for (int k = 0; k < KT; k++) {
            unsigned long long bv = *(const unsigned long long*)&sB[buf][k][lane * 2];
            ulonglong2 A01 = *(const ulonglong2*)&sA[buf][k][nw0 * 2];       // n0,n1 dup
            ulonglong2 A23 = *(const ulonglong2*)&sA[buf][k][nw0 * 2 + 4];   // n2,n3
            ulonglong2 A45 = *(const ulonglong2*)&sA[buf][k][nw0 * 2 + 8];   // n4,n5
            ulonglong2 A67 = *(const ulonglong2*)&sA[buf][k][nw0 * 2 + 12];  // n6,n7
            ffma2(acc2[0], A01.x, bv);
            ffma2(acc2[1], A01.y, bv);
            ffma2(acc2[2], A23.x, bv);
            ffma2(acc2[3], A23.y, bv);
            ffma2(acc2[4], A45.x, bv);
            ffma2(acc2[5], A45.y, bv);
            ffma2(acc2[6], A67.x, bv);
            ffma2(acc2[7], A67.y, bv);
        }

        if (half == 0) {
            int c0 = kt * KT;
#pragma unroll
            for (int j = 0; j < 4; j++) {
                int idx = tid + j * 128;
                int r = idx >> 4, cc = (idx & 15) * 4;
                float4 v = *(const float4*)&sB[buf][r][cc];
                *(float4*)&obase[(size_t)(c0 + r) * HW + cc] = v;
            }
        }
        __syncthreads();
    }
#undef STAGE_CP

    // per-class max over this warp's 8 n; -FLT_MAX sentinel when class absent
    float* cm = g_cmax + ((size_t)((half * 4 + w) * BATCH + b) * KCLS) * 5376
                + q5376 + px0 + lane * 2;
    float accA[8], accB[8];
#pragma unroll
    for (int j = 0; j < 8; j++) {
        float2 v = unpack2(acc2[j]);
        accA[j] = v.x; accB[j] = v.y;
    }
#pragma unroll
    for (int k = 1; k <= KCLS; k++) {
        float mA = -FLT_MAX, mB = -FLT_MAX;
#pragma unroll
        for (int j = 0; j < 8; j++)
            if (lab[nw0 + j] == k) { mA = fmaxf(mA, accA[j]); mB = fmaxf(mB, accB[j]); }
        *(float2*)&cm[(size_t)(k - 1) * 5376] = make_float2(mA, mB);
    }
}

// ---------------------------------------------------------------------------
// K3: combine NSPL partials, map absent-class sentinel -> 0, write class ch.
// ---------------------------------------------------------------------------
__global__ void k_final(float* __restrict__ out) {
    int t = blockIdx.x * 256 + threadIdx.x;
    if (t >= BATCH * KCLS * 5376) return;
    int q = t % 5376;
    int rest = t / 5376;
    int k = rest % KCLS;
    int b = rest / KCLS;

    float m = -FLT_MAX;
#pragma unroll
    for (int p = 0; p < NSPL; p++)
        m = fmaxf(m, g_cmax[((size_t)(p * BATCH + b) * KCLS + k) * 5376 + q]);
    if (m == -FLT_MAX) m = 0.f;

    int HW, hw, oOff;
    if (q < 4096)      { HW = 4096; hw = q;        oOff = 0; }
    else if (q < 5120) { HW = 1024; hw = q - 4096; oOff = 2179072; }
    else               { HW = 256;  hw = q - 5120; oOff = 2723840; }

    out[oOff + (size_t)(b * (CCH + KCLS) + CCH + k) * HW + hw] = m;
}

// ---------------------------------------------------------------------------
extern "C" void kernel_launch(void* const* d_in, const int* in_sizes, int n_in,
                              void* d_out, int out_size) {
    (void)in_sizes; (void)n_in; (void)out_size;
    const float* x0      = (const float*)d_in[0];
    const float* x1      = (const float*)d_in[1];
    const float* x2      = (const float*)d_in[2];
    const float* centers = (const float*)d_in[3];
    const int*   idx     = (const int*)d_in[4];
    const int*   labels  = (const int*)d_in[5];
    float* out = (float*)d_out;

    k_heat<<<384, 64>>>(centers, idx, labels);
    k_tmpl_part<<<448, 256>>>(x0, x1, x2);
    k_tmpl_reduce<<<384, 256>>>();
    k_cor<<<336, 128>>>(x0, x1, x2, labels, out);
    k_final<<<420, 256>>>(out);
}